// round 1
// baseline (speedup 1.0000x reference)
#include <cuda_runtime.h>
#include <math_constants.h>

// Problem constants (fixed shapes for this problem instance)
#define C   128          // channels (K dim)
#define H   96
#define W   128
#define P   (H * W)      // 12288 pixels per image (M and N dims)

#define BM  128          // L-pixel tile per block
#define BN  128          // R-pixel tile per iteration
#define BK  8            // K chunk
#define NSPLIT 6         // R-dimension split across blocks
#define RCHUNK (P / NSPLIT)   // 2048
#define RT (RCHUNK / BN)      // 16 R tiles per block
#define KC (C / BK)           // 16 K chunks

// Cross-block argmax scratch: packed (ordered-float-key << 14) | (0x3FFF - idx)
__device__ unsigned long long g_best[P];

__device__ __forceinline__ unsigned long long pack_key(float v, int idx) {
    unsigned u = __float_as_uint(v);
    u = (u & 0x80000000u) ? ~u : (u | 0x80000000u);   // monotonic float->uint
    return ((unsigned long long)u << 14) | (unsigned)(0x3FFF - idx);
}

__global__ void init_best_kernel() {
    int p = blockIdx.x * blockDim.x + threadIdx.x;
    if (p < P) g_best[p] = 0ULL;   // below any real packed key
}

__global__ __launch_bounds__(256, 2)
void corr_argmax_kernel(const float* __restrict__ A,   // feat_l: [C][P]
                        const float* __restrict__ B)   // feat_r: [C][P]
{
    __shared__ float As[BK][BM];
    __shared__ float Bs[BK][BN];

    const int mBase  = blockIdx.x * BM;          // L-pixel tile base
    const int rBase0 = blockIdx.y * RCHUNK;      // R chunk base

    const int tid = threadIdx.x;
    const int tx  = tid & 15;    // R-dim thread coord
    const int ty  = tid >> 4;    // L-dim thread coord

    // GMEM load mapping: 256 threads each load one float4 per 8x128 chunk
    const int lrow = tid >> 5;          // 0..7   (k row within chunk)
    const int lcol = (tid & 31) * 4;    // 0..124 (pixel col within tile)

    const float* Aptr = A + (size_t)lrow * P + mBase  + lcol;
    const float* Bptr = B + (size_t)lrow * P + rBase0 + lcol;

    // Running per-row best across all R tiles of this block.
    // Thread's 8 L-rows: i<4 -> ty*4+i ; i>=4 -> 64+ty*4+(i-4)
    float runval[8];
    int   runidx[8];
    #pragma unroll
    for (int i = 0; i < 8; i++) { runval[i] = -CUDART_INF_F; runidx[i] = 0; }

    // Prefetch chunk (rt=0, kc=0)
    float4 na = *(const float4*)(Aptr);
    float4 nb = *(const float4*)(Bptr);

    for (int rt = 0; rt < RT; rt++) {
        const int rBase = rBase0 + rt * BN;

        float acc[8][8];
        #pragma unroll
        for (int i = 0; i < 8; i++)
            #pragma unroll
            for (int j = 0; j < 8; j++)
                acc[i][j] = 0.0f;

        for (int kc = 0; kc < KC; kc++) {
            __syncthreads();
            *(float4*)&As[lrow][lcol] = na;
            *(float4*)&Bs[lrow][lcol] = nb;
            __syncthreads();

            // Register prefetch of next chunk (hides GMEM/L2 latency)
            int nkc = kc + 1, nrt = rt;
            if (nkc == KC) { nkc = 0; nrt++; }
            if (nrt < RT) {
                na = *(const float4*)(Aptr + (size_t)nkc * BK * P);
                nb = *(const float4*)(Bptr + (size_t)nkc * BK * P + nrt * BN);
            }

            #pragma unroll
            for (int kk = 0; kk < BK; kk++) {
                float a[8], b[8];
                *(float4*)&a[0] = *(const float4*)&As[kk][ty * 4];
                *(float4*)&a[4] = *(const float4*)&As[kk][64 + ty * 4];
                *(float4*)&b[0] = *(const float4*)&Bs[kk][tx * 4];
                *(float4*)&b[4] = *(const float4*)&Bs[kk][64 + tx * 4];
                #pragma unroll
                for (int i = 0; i < 8; i++)
                    #pragma unroll
                    for (int j = 0; j < 8; j++)
                        acc[i][j] = fmaf(a[i], b[j], acc[i][j]);
            }
        }

        // Fused epilogue: running max/argmax per L-row.
        // Columns scanned in increasing global index order -> strict '>'
        // keeps the earliest index (matches jnp.argmax).
        #pragma unroll
        for (int i = 0; i < 8; i++) {
            float bv = runval[i];
            int   bi = runidx[i];
            #pragma unroll
            for (int j = 0; j < 8; j++) {
                int col = rBase + ((j < 4) ? (tx * 4 + j) : (64 + tx * 4 + (j - 4)));
                float v = acc[i][j];
                if (v > bv) { bv = v; bi = col; }
            }
            runval[i] = bv;
            runidx[i] = bi;
        }
    }

    // Reduce across the 16 tx-threads sharing the same row set.
    // Lanes 0-15 have one ty, lanes 16-31 the next; xor offsets <16 stay in-half.
    #pragma unroll
    for (int off = 1; off < 16; off <<= 1) {
        #pragma unroll
        for (int i = 0; i < 8; i++) {
            float ov = __shfl_xor_sync(0xFFFFFFFFu, runval[i], off);
            int   oi = __shfl_xor_sync(0xFFFFFFFFu, runidx[i], off);
            if (ov > runval[i] || (ov == runval[i] && oi < runidx[i])) {
                runval[i] = ov;
                runidx[i] = oi;
            }
        }
    }

    if (tx == 0) {
        #pragma unroll
        for (int i = 0; i < 8; i++) {
            int row  = (i < 4) ? (ty * 4 + i) : (64 + ty * 4 + (i - 4));
            int grow = mBase + row;
            atomicMax(&g_best[grow], pack_key(runval[i], runidx[i]));
        }
    }
}

__global__ void decode_kernel(float* __restrict__ out,
                              const int* __restrict__ sxp,
                              const int* __restrict__ syp,
                              int has_scale)
{
    int p = blockIdx.x * blockDim.x + threadIdx.x;
    if (p >= P) return;
    int sx = has_scale ? sxp[0] : 4;
    int sy = has_scale ? syp[0] : 4;

    unsigned long long pk = g_best[p];
    int idx = 0x3FFF - (int)(pk & 0x3FFFULL);
    unsigned u = (unsigned)(pk >> 14);
    unsigned f = (u & 0x80000000u) ? (u ^ 0x80000000u) : ~u;
    float val = __uint_as_float(f);

    int h = p >> 7;      // p / W  (W=128)
    int w = p & 127;     // p % W
    int i = idx >> 7;    // idx / W_R
    int j = idx & 127;   // idx % W_R

    // flow [H,W,2] then flow_cost [H,W], concatenated
    out[2 * p]     = (float)(w - j * sx);   // u = -(j*sx - w)
    out[2 * p + 1] = (float)(h - i * sy);   // v = -(i*sy - h)
    out[2 * P + p] = val;
}

extern "C" void kernel_launch(void* const* d_in, const int* in_sizes, int n_in,
                              void* d_out, int out_size)
{
    const float* A = (const float*)d_in[0];   // feat_l
    const float* B = (const float*)d_in[1];   // feat_r
    const int* sx = (n_in > 2) ? (const int*)d_in[2] : nullptr;
    const int* sy = (n_in > 3) ? (const int*)d_in[3] : nullptr;
    int has_scale = (n_in > 3) ? 1 : 0;

    init_best_kernel<<<(P + 255) / 256, 256>>>();

    dim3 grid(P / BM, NSPLIT);   // 96 x 6 = 576 blocks
    corr_argmax_kernel<<<grid, 256>>>(A, B);

    decode_kernel<<<(P + 255) / 256, 256>>>((float*)d_out, sx, sy, has_scale);
}

// round 3
// speedup vs baseline: 1.5623x; 1.5623x over previous
#include <cuda_runtime.h>
#include <cuda_bf16.h>
#include <math_constants.h>
#include <cstdint>

#define C 128
#define H 96
#define W 128
#define P (H * W)            // 12288
#define NSPL 3
#define NCHUNK (P / NSPL)    // 4096
#define NT (NCHUNK / 128)    // 32 N-tiles per CTA
#define IDESC 0x8200490u     // f32 accum, bf16 x bf16, N=128, M=128 (cg1)

// tcgen05 is an arch-SPECIFIC feature: only valid when compiling for sm_103a.
#if defined(__CUDA_ARCH__) && defined(__CUDA_ARCH_FEAT_SM103_ALL)
#define HAS_TC 1
#else
#define HAS_TC 0
#endif

// ---------------- device globals (scratch; no allocation allowed) ----------
__device__ unsigned long long g_best[P];
__device__ __nv_bfloat16 g_Asp[3ull * P * C];   // [lvl][pixel][channel]
__device__ __nv_bfloat16 g_Bsp[3ull * P * C];

// ---------------- smem layout (dynamic) ------------------------------------
#define SM_TMEM 0
#define SM_MBAR_CHUNK 16     // 2 x 8B
#define SM_MBAR_D     32     // 2 x 8B
#define SM_MBAR_E     48     // 2 x 8B
#define SM_A   1024                      // 3 x 32768
#define SM_B   (SM_A + 3 * 32768)        // 2 parities x 3 lvls x 16384
#define SMEM_TOTAL (SM_B + 2 * 49152)    // 197632 bytes

// ---------------- PTX helpers ----------------------------------------------
__device__ __forceinline__ uint32_t smem_u32(const void* p) {
    uint32_t a;
    asm("{ .reg .u64 t; cvta.to.shared.u64 t, %1; cvt.u32.u64 %0, t; }"
        : "=r"(a) : "l"(p));
    return a;
}
__device__ __forceinline__ uint32_t swz(uint32_t b) { return b ^ ((b >> 3) & 0x70); }
__device__ __forceinline__ uint32_t a_off(int m, int k) {
    // blocked atom layout: atom = 8 rows x 64 bf16 (1024B); 16 atom-rows x 2 atom-cols
    return ((uint32_t)((m >> 3) + (k >> 6) * 16)) * 1024u + (uint32_t)(m & 7) * 128u
         + (uint32_t)(k & 63) * 2u;
}
__device__ __forceinline__ uint64_t mk_desc(uint32_t addr) {
    // SW128, Blackwell version=1, LBO=1, SBO=64 (K-major)
    return ((uint64_t)2 << 61) | ((uint64_t)1 << 46) | ((uint64_t)64 << 32)
         | ((uint64_t)1 << 16) | ((addr >> 4) & 0x3FFF);
}

__device__ __forceinline__ void mbar_init(uint32_t a, uint32_t n) {
#if HAS_TC
    asm volatile("mbarrier.init.shared.b64 [%0], %1;" :: "r"(a), "r"(n) : "memory");
#endif
}
__device__ __forceinline__ void mbar_arrive(uint32_t a) {
#if HAS_TC
    asm volatile("mbarrier.arrive.shared.b64 _, [%0];" :: "r"(a) : "memory");
#endif
}
__device__ __forceinline__ void tc_commit(uint32_t a) {
#if HAS_TC
    asm volatile("tcgen05.commit.cta_group::1.mbarrier::arrive::one.shared::cluster.b64 [%0];"
                 :: "r"(a) : "memory");
#endif
}
__device__ __forceinline__ void tc_fence_after()  {
#if HAS_TC
    asm volatile("tcgen05.fence::after_thread_sync;" ::: "memory");
#endif
}
__device__ __forceinline__ void tc_fence_before() {
#if HAS_TC
    asm volatile("tcgen05.fence::before_thread_sync;" ::: "memory");
#endif
}
__device__ __forceinline__ void tc_wait_ld() {
#if HAS_TC
    asm volatile("tcgen05.wait::ld.sync.aligned;" ::: "memory");
#endif
}
__device__ __forceinline__ void fence_async() {
#if HAS_TC
    asm volatile("fence.proxy.async.shared::cta;" ::: "memory");
#endif
}
__device__ __forceinline__ void tc_alloc(uint32_t dst, uint32_t ncols) {
#if HAS_TC
    asm volatile("tcgen05.alloc.cta_group::1.sync.aligned.shared::cta.b32 [%0], %1;"
                 :: "r"(dst), "r"(ncols) : "memory");
#endif
}
__device__ __forceinline__ void tc_dealloc(uint32_t tmem, uint32_t ncols) {
#if HAS_TC
    asm volatile("tcgen05.relinquish_alloc_permit.cta_group::1.sync.aligned;");
    asm volatile("tcgen05.dealloc.cta_group::1.sync.aligned.b32 %0, %1;"
                 :: "r"(tmem), "r"(ncols));
#endif
}
__device__ __forceinline__ void mbar_wait(uint32_t mbar, uint32_t parity) {
#if HAS_TC
    uint32_t done;
    asm volatile(
        "{\n\t.reg .pred p;\n\t"
        "mbarrier.try_wait.parity.acquire.cta.shared::cta.b64 p, [%1], %2;\n\t"
        "selp.b32 %0, 1, 0, p;\n\t}"
        : "=r"(done) : "r"(mbar), "r"(parity) : "memory");
    if (!done) {
        asm volatile(
            "{\n\t.reg .pred P1;\n\t"
            "W_%=:\n\t"
            "mbarrier.try_wait.parity.acquire.cta.shared::cta.b64 P1, [%0], %1, 0x989680;\n\t"
            "@P1 bra.uni D_%=;\n\t"
            "bra.uni W_%=;\n\t"
            "D_%=:\n\t}"
            :: "r"(mbar), "r"(parity) : "memory");
    }
#endif
}
__device__ __forceinline__ void mma_f16_ss(uint32_t d, uint64_t ad, uint64_t bd,
                                           uint32_t idesc, bool en) {
#if HAS_TC
    uint32_t e = en ? 1u : 0u;
    asm volatile(
        "{\n\t.reg .pred p;\n\tsetp.ne.u32 p, %5, 0;\n\t"
        "tcgen05.mma.cta_group::1.kind::f16 [%0], %1, %2, %3, {%4,%4,%4,%4}, p;\n\t}"
        :: "r"(d), "l"(ad), "l"(bd), "r"(idesc), "r"(0u), "r"(e) : "memory");
#endif
}
__device__ __forceinline__ void ldtm_x32(uint32_t* r, uint32_t ta) {
#if HAS_TC
    asm volatile(
        "tcgen05.ld.sync.aligned.32x32b.x32.b32 "
        "{%0,%1,%2,%3,%4,%5,%6,%7,%8,%9,%10,%11,%12,%13,%14,%15,"
        "%16,%17,%18,%19,%20,%21,%22,%23,%24,%25,%26,%27,%28,%29,%30,%31}, [%32];"
        : "=r"(r[0]), "=r"(r[1]), "=r"(r[2]), "=r"(r[3]), "=r"(r[4]), "=r"(r[5]),
          "=r"(r[6]), "=r"(r[7]), "=r"(r[8]), "=r"(r[9]), "=r"(r[10]), "=r"(r[11]),
          "=r"(r[12]), "=r"(r[13]), "=r"(r[14]), "=r"(r[15]), "=r"(r[16]), "=r"(r[17]),
          "=r"(r[18]), "=r"(r[19]), "=r"(r[20]), "=r"(r[21]), "=r"(r[22]), "=r"(r[23]),
          "=r"(r[24]), "=r"(r[25]), "=r"(r[26]), "=r"(r[27]), "=r"(r[28]), "=r"(r[29]),
          "=r"(r[30]), "=r"(r[31])
        : "r"(ta));
#endif
}

// ---------------- argmax packing -------------------------------------------
__device__ __forceinline__ unsigned long long pack_key(float v, int idx) {
    unsigned u = __float_as_uint(v);
    u = (u & 0x80000000u) ? ~u : (u | 0x80000000u);
    return ((unsigned long long)u << 14) | (unsigned)(0x3FFF - idx);
}

__global__ void init_best_kernel() {
    int p = blockIdx.x * blockDim.x + threadIdx.x;
    if (p < P) g_best[p] = 0ULL;
}

// ---------------- split fp32 -> 3 x bf16, transposed to [lvl][p][k] --------
__global__ void split_kernel(const float* __restrict__ in, __nv_bfloat16* __restrict__ out) {
    __shared__ float tile[32][33];
    const int pB = blockIdx.x * 32, kB = blockIdx.y * 32;
    const int tx = threadIdx.x, ty = threadIdx.y;     // 32 x 8
    #pragma unroll
    for (int r = 0; r < 32; r += 8)
        tile[ty + r][tx] = in[(size_t)(kB + ty + r) * P + pB + tx];
    __syncthreads();
    #pragma unroll
    for (int r = 0; r < 32; r += 8) {
        int py = ty + r;
        float x = tile[tx][py];                        // in[kB+tx][pB+py]
        __nv_bfloat16 b0 = __float2bfloat16(x);
        float r1 = x - __bfloat162float(b0);
        __nv_bfloat16 b1 = __float2bfloat16(r1);
        float r2 = r1 - __bfloat162float(b1);
        __nv_bfloat16 b2 = __float2bfloat16(r2);
        size_t base = (size_t)(pB + py) * C + (kB + tx);
        out[base] = b0;
        out[(size_t)P * C + base] = b1;
        out[2ull * P * C + base] = b2;
    }
}

// ---------------- main GEMM + fused argmax -----------------------------------
// Same signature/launch config for both paths: grid (96,3), 256 threads,
// SMEM_TOTAL dynamic smem.
__global__ __launch_bounds__(256, 1) void corr_kernel(const float* __restrict__ A32,
                                                      const float* __restrict__ B32) {
    extern __shared__ char smem[];
    const int tid = threadIdx.x;
    const int mBase = blockIdx.x * 128;
    const int rBase0 = blockIdx.y * NCHUNK;

#if HAS_TC
    // ======================= tcgen05 path =====================================
    const uint32_t sb = smem_u32(smem);
    const int wid = tid >> 5;

    if (wid == 0) tc_alloc(sb + SM_TMEM, 256u);
    if (tid == 0) {
        mbar_init(sb + SM_MBAR_CHUNK + 0, 1);
        mbar_init(sb + SM_MBAR_CHUNK + 8, 1);
        mbar_init(sb + SM_MBAR_D + 0, 1);
        mbar_init(sb + SM_MBAR_D + 8, 1);
        mbar_init(sb + SM_MBAR_E + 0, 4);
        mbar_init(sb + SM_MBAR_E + 8, 4);
    }

    // Load persistent A tiles: 3 lvls x 128 rows x 128 k-cols bf16, blocked+SW128
    for (int e = tid; e < 6144; e += 256) {
        int kq = e & 15, m = (e >> 4) & 127, lvl = e >> 11;
        float4 v = *(const float4*)&g_Asp[(size_t)lvl * P * C + (size_t)(mBase + m) * C + kq * 8];
        *(float4*)(smem + SM_A + lvl * 32768 + swz(a_off(m, kq * 8))) = v;
    }
    fence_async();
    __syncthreads();

    uint32_t tmem;
    asm volatile("ld.shared.b32 %0, [%1];" : "=r"(tmem) : "r"(sb + SM_TMEM));

    if (wid >= 4) {
        // -------- producer: B-chunk loaders + MMA issue --------
        const int tl = tid - 128;
        int chunk_phase[2] = {0, 0};
        int e_phase[2] = {0, 0};
        uint64_t adesc[3];
        adesc[0] = mk_desc(sb + SM_A);
        adesc[1] = mk_desc(sb + SM_A + 32768);
        adesc[2] = mk_desc(sb + SM_A + 65536);
        const int sa[6]  = {0, 0, 1, 1, 0, 2};
        const int sbl[6] = {0, 1, 0, 1, 2, 0};

        for (int ck = 0; ck < 2 * NT; ck++) {
            const int t = ck >> 1, kc = ck & 1, pbuf = ck & 1;
            if (ck >= 2) {
                mbar_wait(sb + SM_MBAR_CHUNK + 8 * pbuf, chunk_phase[pbuf]);
                chunk_phase[pbuf] ^= 1;
            }
            const uint32_t bbase = SM_B + pbuf * 49152;
            for (int e2 = tl; e2 < 3072; e2 += 128) {
                int kq = e2 & 7, n = (e2 >> 3) & 127, lvl = e2 >> 10;
                float4 v = *(const float4*)&g_Bsp[(size_t)lvl * P * C
                           + (size_t)(rBase0 + t * 128 + n) * C + kc * 64 + kq * 8];
                *(float4*)(smem + bbase + lvl * 16384 + swz(n * 128 + kq * 16)) = v;
            }
            fence_async();
            asm volatile("bar.sync 1, 128;" ::: "memory");

            if (tid == 128) {
                if (kc == 0 && t >= 2) {
                    mbar_wait(sb + SM_MBAR_E + 8 * (t & 1), e_phase[t & 1]);
                    e_phase[t & 1] ^= 1;
                    tc_fence_after();
                }
                const uint32_t dt = tmem + (t & 1) * 128;
                #pragma unroll
                for (int pr = 0; pr < 6; pr++) {
                    uint64_t ad = adesc[sa[pr]];
                    uint64_t bd = mk_desc(sb + bbase + sbl[pr] * 16384);
                    #pragma unroll
                    for (int ks = 0; ks < 4; ks++) {
                        int s = kc * 4 + ks;
                        mma_f16_ss(dt, ad + (uint64_t)((s >> 2) * 1024 + (s & 3) * 2),
                                   bd + (uint64_t)(ks * 2), IDESC,
                                   !(kc == 0 && pr == 0 && ks == 0));
                    }
                }
                tc_commit(sb + SM_MBAR_CHUNK + 8 * pbuf);
                if (kc == 1) tc_commit(sb + SM_MBAR_D + 8 * (t & 1));
            }
        }
    } else {
        // -------- consumer: LDTM + fused running argmax --------
        float bv = -CUDART_INF_F;
        int bi = 0;
        int d_phase[2] = {0, 0};
        const uint32_t woff = ((uint32_t)(tid >> 5)) << 21;   // TMEM subpartition

        for (int t = 0; t < NT; t++) {
            mbar_wait(sb + SM_MBAR_D + 8 * (t & 1), d_phase[t & 1]);
            d_phase[t & 1] ^= 1;
            tc_fence_after();
            const uint32_t dt = tmem + (t & 1) * 128;
            #pragma unroll
            for (int cb = 0; cb < 128; cb += 32) {
                uint32_t r[32];
                ldtm_x32(r, dt + cb + woff);
                tc_wait_ld();
                const int colbase = rBase0 + t * 128 + cb;
                #pragma unroll
                for (int j = 0; j < 32; j++) {
                    float v = __uint_as_float(r[j]);
                    if (v > bv) { bv = v; bi = colbase + j; }
                }
            }
            tc_fence_before();
            if ((tid & 31) == 0) mbar_arrive(sb + SM_MBAR_E + 8 * (t & 1));
        }
        atomicMax(&g_best[mBase + tid], pack_key(bv, bi));
    }

    __syncthreads();
    if (wid == 0) tc_dealloc(tmem, 256u);

#else
    // ======================= FFMA fallback (non-'a' target) ==================
    // Round-1 structure adapted to grid (96,3): RT = 32 N-tiles of 128.
    float (*As)[128] = (float(*)[128])(smem);            // [8][128]
    float (*Bs)[128] = (float(*)[128])(smem + 4096);     // [8][128]

    const int tx = tid & 15;
    const int ty = tid >> 4;
    const int lrow = tid >> 5;
    const int lcol = (tid & 31) * 4;

    const float* Aptr = A32 + (size_t)lrow * P + mBase  + lcol;
    const float* Bptr = B32 + (size_t)lrow * P + rBase0 + lcol;

    float runval[8];
    int   runidx[8];
    #pragma unroll
    for (int i = 0; i < 8; i++) { runval[i] = -CUDART_INF_F; runidx[i] = 0; }

    float4 na = *(const float4*)(Aptr);
    float4 nb = *(const float4*)(Bptr);

    const int RT2 = NCHUNK / 128;   // 32
    for (int rt = 0; rt < RT2; rt++) {
        const int rBase = rBase0 + rt * 128;
        float acc[8][8];
        #pragma unroll
        for (int i = 0; i < 8; i++)
            #pragma unroll
            for (int j = 0; j < 8; j++) acc[i][j] = 0.0f;

        for (int kc = 0; kc < 16; kc++) {
            __syncthreads();
            *(float4*)&As[lrow][lcol] = na;
            *(float4*)&Bs[lrow][lcol] = nb;
            __syncthreads();

            int nkc = kc + 1, nrt = rt;
            if (nkc == 16) { nkc = 0; nrt++; }
            if (nrt < RT2) {
                na = *(const float4*)(Aptr + (size_t)nkc * 8 * P);
                nb = *(const float4*)(Bptr + (size_t)nkc * 8 * P + nrt * 128);
            }

            #pragma unroll
            for (int kk = 0; kk < 8; kk++) {
                float a[8], b[8];
                *(float4*)&a[0] = *(const float4*)&As[kk][ty * 4];
                *(float4*)&a[4] = *(const float4*)&As[kk][64 + ty * 4];
                *(float4*)&b[0] = *(const float4*)&Bs[kk][tx * 4];
                *(float4*)&b[4] = *(const float4*)&Bs[kk][64 + tx * 4];
                #pragma unroll
                for (int i = 0; i < 8; i++)
                    #pragma unroll
                    for (int j = 0; j < 8; j++)
                        acc[i][j] = fmaf(a[i], b[j], acc[i][j]);
            }
        }

        #pragma unroll
        for (int i = 0; i < 8; i++) {
            float bv = runval[i];
            int   bi = runidx[i];
            #pragma unroll
            for (int j = 0; j < 8; j++) {
                int col = rBase + ((j < 4) ? (tx * 4 + j) : (64 + tx * 4 + (j - 4)));
                float v = acc[i][j];
                if (v > bv) { bv = v; bi = col; }
            }
            runval[i] = bv;
            runidx[i] = bi;
        }
    }

    #pragma unroll
    for (int off = 1; off < 16; off <<= 1) {
        #pragma unroll
        for (int i = 0; i < 8; i++) {
            float ov = __shfl_xor_sync(0xFFFFFFFFu, runval[i], off);
            int   oi = __shfl_xor_sync(0xFFFFFFFFu, runidx[i], off);
            if (ov > runval[i] || (ov == runval[i] && oi < runidx[i])) {
                runval[i] = ov;
                runidx[i] = oi;
            }
        }
    }
    if (tx == 0) {
        #pragma unroll
        for (int i = 0; i < 8; i++) {
            int row = (i < 4) ? (ty * 4 + i) : (64 + ty * 4 + (i - 4));
            atomicMax(&g_best[mBase + row], pack_key(runval[i], runidx[i]));
        }
    }
#endif
}

// ---------------- decode ----------------------------------------------------
__global__ void decode_kernel(float* __restrict__ out,
                              const int* __restrict__ sxp,
                              const int* __restrict__ syp,
                              int has_scale) {
    int p = blockIdx.x * blockDim.x + threadIdx.x;
    if (p >= P) return;
    int sx = has_scale ? sxp[0] : 4;
    int sy = has_scale ? syp[0] : 4;

    unsigned long long pk = g_best[p];
    int idx = 0x3FFF - (int)(pk & 0x3FFFULL);
    unsigned u = (unsigned)(pk >> 14);
    unsigned f = (u & 0x80000000u) ? (u ^ 0x80000000u) : ~u;
    float val = __uint_as_float(f);

    int h = p >> 7, w = p & 127;
    int i = idx >> 7, j = idx & 127;

    out[2 * p]     = (float)(w - j * sx);
    out[2 * p + 1] = (float)(h - i * sy);
    out[2 * P + p] = val;
}

// ---------------- launch -----------------------------------------------------
extern "C" void kernel_launch(void* const* d_in, const int* in_sizes, int n_in,
                              void* d_out, int out_size) {
    const float* A = (const float*)d_in[0];
    const float* B = (const float*)d_in[1];
    const int* sx = (n_in > 2) ? (const int*)d_in[2] : nullptr;
    const int* sy = (n_in > 3) ? (const int*)d_in[3] : nullptr;
    int has_scale = (n_in > 3) ? 1 : 0;

    cudaFuncSetAttribute(corr_kernel, cudaFuncAttributeMaxDynamicSharedMemorySize, SMEM_TOTAL);

    __nv_bfloat16* dAs;
    __nv_bfloat16* dBs;
    cudaGetSymbolAddress((void**)&dAs, g_Asp);
    cudaGetSymbolAddress((void**)&dBs, g_Bsp);

    dim3 sgrid(P / 32, C / 32), sblk(32, 8);
    split_kernel<<<sgrid, sblk>>>(A, dAs);
    split_kernel<<<sgrid, sblk>>>(B, dBs);

    init_best_kernel<<<(P + 255) / 256, 256>>>();

    dim3 grid(P / 128, NSPL);   // 96 x 3 = 288 CTAs
    corr_kernel<<<grid, 256, SMEM_TOTAL>>>(A, B);

    decode_kernel<<<(P + 255) / 256, 256>>>((float*)d_out, sx, sy, has_scale);
}

// round 4
// speedup vs baseline: 4.4537x; 2.8507x over previous
#include <cuda_runtime.h>
#include <cuda_bf16.h>
#include <math_constants.h>
#include <cstdint>

#define C 128
#define H 96
#define W 128
#define P (H * W)            // 12288
#define NSPL 3
#define NCHUNK (P / NSPL)    // 4096
#define NT (NCHUNK / 128)    // 32 N-tiles per CTA
#define IDESC 0x8200490u     // f32 accum, bf16 x bf16, N=128, M=128 (cg1)
#define NTHREADS 288

// tcgen05 is an arch-SPECIFIC feature: only valid when compiling for sm_103a.
#if defined(__CUDA_ARCH__) && defined(__CUDA_ARCH_FEAT_SM103_ALL)
#define HAS_TC 1
#else
#define HAS_TC 0
#endif

// ---------------- device globals (scratch; no allocation allowed) ----------
__device__ unsigned long long g_best[P];
__device__ __nv_bfloat16 g_Asp[3ull * P * C];   // [lvl][pixel][channel]
__device__ __nv_bfloat16 g_Bsp[3ull * P * C];

// ---------------- smem layout (dynamic) ------------------------------------
#define SM_TMEM  0
#define MB_FULL  16      // 2 x 8B  (loaders -> MMA, count=128)
#define MB_EMPTY 32      // 2 x 8B  (MMA commit -> loaders, count=1)
#define MB_D     48      // 2 x 8B  (MMA commit -> consumers, count=1)
#define MB_E     64      // 2 x 8B  (consumers -> MMA, count=4)
#define SM_A     1024                    // 3 x 32768
#define SM_B     (SM_A + 3 * 32768)      // 2 bufs x 3 lvls x 16384
#define SMEM_TOTAL (SM_B + 2 * 49152)    // 197632 bytes

// ---------------- PTX helpers ----------------------------------------------
__device__ __forceinline__ uint32_t smem_u32(const void* p) {
    uint32_t a;
    asm("{ .reg .u64 t; cvta.to.shared.u64 t, %1; cvt.u32.u64 %0, t; }"
        : "=r"(a) : "l"(p));
    return a;
}
__device__ __forceinline__ uint32_t swz(uint32_t b) { return b ^ ((b >> 3) & 0x70); }
__device__ __forceinline__ uint32_t a_off(int m, int k) {
    // blocked atom layout: atom = 8 rows x 64 bf16 (1024B); 16 atom-rows x 2 atom-cols
    return ((uint32_t)((m >> 3) + (k >> 6) * 16)) * 1024u + (uint32_t)(m & 7) * 128u
         + (uint32_t)(k & 63) * 2u;
}
__device__ __forceinline__ uint64_t mk_desc(uint32_t addr) {
    // SW128, Blackwell version=1, LBO=1, SBO=64 (K-major)
    return ((uint64_t)2 << 61) | ((uint64_t)1 << 46) | ((uint64_t)64 << 32)
         | ((uint64_t)1 << 16) | ((addr >> 4) & 0x3FFF);
}

__device__ __forceinline__ void cp_async16(uint32_t dst, const void* src) {
    asm volatile("cp.async.cg.shared.global [%0], [%1], 16;"
                 :: "r"(dst), "l"(src) : "memory");
}
__device__ __forceinline__ void cp_commit() {
    asm volatile("cp.async.commit_group;" ::: "memory");
}
__device__ __forceinline__ void cp_wait0() {
    asm volatile("cp.async.wait_group 0;" ::: "memory");
}

__device__ __forceinline__ void mbar_init(uint32_t a, uint32_t n) {
#if HAS_TC
    asm volatile("mbarrier.init.shared.b64 [%0], %1;" :: "r"(a), "r"(n) : "memory");
#endif
}
__device__ __forceinline__ void mbar_arrive(uint32_t a) {
#if HAS_TC
    asm volatile("mbarrier.arrive.shared.b64 _, [%0];" :: "r"(a) : "memory");
#endif
}
__device__ __forceinline__ void tc_commit(uint32_t a) {
#if HAS_TC
    asm volatile("tcgen05.commit.cta_group::1.mbarrier::arrive::one.shared::cluster.b64 [%0];"
                 :: "r"(a) : "memory");
#endif
}
__device__ __forceinline__ void tc_fence_after()  {
#if HAS_TC
    asm volatile("tcgen05.fence::after_thread_sync;" ::: "memory");
#endif
}
__device__ __forceinline__ void tc_fence_before() {
#if HAS_TC
    asm volatile("tcgen05.fence::before_thread_sync;" ::: "memory");
#endif
}
__device__ __forceinline__ void tc_wait_ld() {
#if HAS_TC
    asm volatile("tcgen05.wait::ld.sync.aligned;" ::: "memory");
#endif
}
__device__ __forceinline__ void fence_async() {
#if HAS_TC
    asm volatile("fence.proxy.async.shared::cta;" ::: "memory");
#endif
}
__device__ __forceinline__ void tc_alloc(uint32_t dst, uint32_t ncols) {
#if HAS_TC
    asm volatile("tcgen05.alloc.cta_group::1.sync.aligned.shared::cta.b32 [%0], %1;"
                 :: "r"(dst), "r"(ncols) : "memory");
#endif
}
__device__ __forceinline__ void tc_dealloc(uint32_t tmem, uint32_t ncols) {
#if HAS_TC
    asm volatile("tcgen05.relinquish_alloc_permit.cta_group::1.sync.aligned;");
    asm volatile("tcgen05.dealloc.cta_group::1.sync.aligned.b32 %0, %1;"
                 :: "r"(tmem), "r"(ncols));
#endif
}
__device__ __forceinline__ void mbar_wait(uint32_t mbar, uint32_t parity) {
#if HAS_TC
    uint32_t done;
    asm volatile(
        "{\n\t.reg .pred p;\n\t"
        "mbarrier.try_wait.parity.acquire.cta.shared::cta.b64 p, [%1], %2;\n\t"
        "selp.b32 %0, 1, 0, p;\n\t}"
        : "=r"(done) : "r"(mbar), "r"(parity) : "memory");
    if (!done) {
        asm volatile(
            "{\n\t.reg .pred P1;\n\t"
            "W_%=:\n\t"
            "mbarrier.try_wait.parity.acquire.cta.shared::cta.b64 P1, [%0], %1, 0x989680;\n\t"
            "@P1 bra.uni D_%=;\n\t"
            "bra.uni W_%=;\n\t"
            "D_%=:\n\t}"
            :: "r"(mbar), "r"(parity) : "memory");
    }
#endif
}
__device__ __forceinline__ void mma_f16_ss(uint32_t d, uint64_t ad, uint64_t bd,
                                           uint32_t idesc, bool en) {
#if HAS_TC
    uint32_t e = en ? 1u : 0u;
    asm volatile(
        "{\n\t.reg .pred p;\n\tsetp.ne.u32 p, %5, 0;\n\t"
        "tcgen05.mma.cta_group::1.kind::f16 [%0], %1, %2, %3, {%4,%4,%4,%4}, p;\n\t}"
        :: "r"(d), "l"(ad), "l"(bd), "r"(idesc), "r"(0u), "r"(e) : "memory");
#endif
}
__device__ __forceinline__ void ldtm_x32(uint32_t* r, uint32_t ta) {
#if HAS_TC
    asm volatile(
        "tcgen05.ld.sync.aligned.32x32b.x32.b32 "
        "{%0,%1,%2,%3,%4,%5,%6,%7,%8,%9,%10,%11,%12,%13,%14,%15,"
        "%16,%17,%18,%19,%20,%21,%22,%23,%24,%25,%26,%27,%28,%29,%30,%31}, [%32];"
        : "=r"(r[0]), "=r"(r[1]), "=r"(r[2]), "=r"(r[3]), "=r"(r[4]), "=r"(r[5]),
          "=r"(r[6]), "=r"(r[7]), "=r"(r[8]), "=r"(r[9]), "=r"(r[10]), "=r"(r[11]),
          "=r"(r[12]), "=r"(r[13]), "=r"(r[14]), "=r"(r[15]), "=r"(r[16]), "=r"(r[17]),
          "=r"(r[18]), "=r"(r[19]), "=r"(r[20]), "=r"(r[21]), "=r"(r[22]), "=r"(r[23]),
          "=r"(r[24]), "=r"(r[25]), "=r"(r[26]), "=r"(r[27]), "=r"(r[28]), "=r"(r[29]),
          "=r"(r[30]), "=r"(r[31])
        : "r"(ta));
#endif
}

// ---------------- argmax packing -------------------------------------------
__device__ __forceinline__ unsigned long long pack_key(float v, int idx) {
    unsigned u = __float_as_uint(v);
    u = (u & 0x80000000u) ? ~u : (u | 0x80000000u);
    return ((unsigned long long)u << 14) | (unsigned)(0x3FFF - idx);
}

__global__ void init_best_kernel() {
    int p = blockIdx.x * blockDim.x + threadIdx.x;
    if (p < P) g_best[p] = 0ULL;
}

// ---------------- split fp32 -> 3 x bf16, transposed to [lvl][p][k] --------
__global__ void split_kernel(const float* __restrict__ in, __nv_bfloat16* __restrict__ out) {
    __shared__ float tile[32][33];
    const int pB = blockIdx.x * 32, kB = blockIdx.y * 32;
    const int tx = threadIdx.x, ty = threadIdx.y;     // 32 x 8
    #pragma unroll
    for (int r = 0; r < 32; r += 8)
        tile[ty + r][tx] = in[(size_t)(kB + ty + r) * P + pB + tx];
    __syncthreads();
    #pragma unroll
    for (int r = 0; r < 32; r += 8) {
        int py = ty + r;
        float x = tile[tx][py];                        // in[kB+tx][pB+py]
        __nv_bfloat16 b0 = __float2bfloat16(x);
        float r1 = x - __bfloat162float(b0);
        __nv_bfloat16 b1 = __float2bfloat16(r1);
        float r2 = r1 - __bfloat162float(b1);
        __nv_bfloat16 b2 = __float2bfloat16(r2);
        size_t base = (size_t)(pB + py) * C + (kB + tx);
        out[base] = b0;
        out[(size_t)P * C + base] = b1;
        out[2ull * P * C + base] = b2;
    }
}

// ---------------- main GEMM + fused argmax -----------------------------------
// grid (96,3), 288 threads. Roles: warps 0-3 consumer, 4-7 loader, 8 MMA.
__global__ __launch_bounds__(NTHREADS, 1) void corr_kernel(const float* __restrict__ A32,
                                                           const float* __restrict__ B32) {
    extern __shared__ char smem[];
    const int tid = threadIdx.x;
    const int mBase = blockIdx.x * 128;
    const int rBase0 = blockIdx.y * NCHUNK;

#if HAS_TC
    // ======================= tcgen05 path =====================================
    const uint32_t sb = smem_u32(smem);
    const int wid = tid >> 5;

    if (wid == 8) tc_alloc(sb + SM_TMEM, 256u);
    if (tid == 0) {
        mbar_init(sb + MB_FULL + 0, 128);
        mbar_init(sb + MB_FULL + 8, 128);
        mbar_init(sb + MB_EMPTY + 0, 1);
        mbar_init(sb + MB_EMPTY + 8, 1);
        mbar_init(sb + MB_D + 0, 1);
        mbar_init(sb + MB_D + 8, 1);
        mbar_init(sb + MB_E + 0, 4);
        mbar_init(sb + MB_E + 8, 4);
    }

    // A prologue via cp.async: 3 lvls x 128 rows x 128 k-cols bf16, blocked+SW128
    for (int e = tid; e < 6144; e += NTHREADS) {
        int kq16 = e & 15, m = (e >> 4) & 127, lvl = e >> 11;
        const __nv_bfloat16* src = g_Asp + (size_t)lvl * P * C
                                 + (size_t)(mBase + m) * C + kq16 * 8;
        cp_async16(sb + SM_A + lvl * 32768 + swz(a_off(m, kq16 * 8)), src);
    }
    cp_commit();
    cp_wait0();
    fence_async();
    __syncthreads();

    uint32_t tmem;
    asm volatile("ld.shared.b32 %0, [%1];" : "=r"(tmem) : "r"(sb + SM_TMEM));

    if (wid >= 4 && wid < 8) {
        // -------- loaders: stream B chunks via cp.async, run ahead ------------
        const int tl = tid - 128;
        const int kq = tl & 7;                  // fixed per thread
        uint32_t soff[8];
        int njs[8];
        #pragma unroll
        for (int j = 0; j < 8; j++) {
            njs[j] = (((tl >> 3) + 16 * j) & 127);
            soff[j] = swz((uint32_t)njs[j] * 128u + (uint32_t)kq * 16u);
        }
        const __nv_bfloat16* gb0 = g_Bsp + (size_t)rBase0 * C + kq * 8;

        int eph[2] = {1, 1};   // producer phase trick: first wait passes
        for (int ck = 0; ck < 2 * NT; ck++) {
            const int pbuf = ck & 1;
            mbar_wait(sb + MB_EMPTY + 8 * pbuf, (uint32_t)eph[pbuf]);
            eph[pbuf] ^= 1;

            const size_t coff = (size_t)(ck >> 1) * (128 * C) + (size_t)(ck & 1) * 64;
            const uint32_t dl = sb + SM_B + pbuf * 49152;
            #pragma unroll
            for (int l = 0; l < 3; l++) {
                const __nv_bfloat16* g = gb0 + (size_t)l * P * C + coff;
                #pragma unroll
                for (int j = 0; j < 8; j++)
                    cp_async16(dl + l * 16384 + soff[j], g + (size_t)njs[j] * C);
            }
            cp_commit();
            cp_wait0();
            fence_async();
            mbar_arrive(sb + MB_FULL + 8 * pbuf);
        }
    } else if (tid == 256) {
        // -------- dedicated MMA issuer (single thread of warp 8) --------------
        int fph[2] = {0, 0};
        int Eph[2] = {0, 0};
        uint64_t adesc[3];
        adesc[0] = mk_desc(sb + SM_A);
        adesc[1] = mk_desc(sb + SM_A + 32768);
        adesc[2] = mk_desc(sb + SM_A + 65536);
        const int sa[6]  = {0, 0, 1, 1, 0, 2};
        const int sbl[6] = {0, 1, 0, 1, 2, 0};

        for (int ck = 0; ck < 2 * NT; ck++) {
            const int pbuf = ck & 1, t = ck >> 1, kc = ck & 1;
            mbar_wait(sb + MB_FULL + 8 * pbuf, (uint32_t)fph[pbuf]);
            fph[pbuf] ^= 1;
            if (kc == 0 && t >= 2) {
                mbar_wait(sb + MB_E + 8 * (t & 1), (uint32_t)Eph[t & 1]);
                Eph[t & 1] ^= 1;
                tc_fence_after();
            }
            const uint32_t dt = tmem + (t & 1) * 128;
            const uint32_t bb = sb + SM_B + pbuf * 49152;
            #pragma unroll
            for (int pr = 0; pr < 6; pr++) {
                uint64_t ad = adesc[sa[pr]];
                uint64_t bd = mk_desc(bb + sbl[pr] * 16384);
                #pragma unroll
                for (int ks = 0; ks < 4; ks++) {
                    int s = kc * 4 + ks;
                    mma_f16_ss(dt, ad + (uint64_t)((s >> 2) * 1024 + (s & 3) * 2),
                               bd + (uint64_t)(ks * 2), IDESC,
                               !(kc == 0 && pr == 0 && ks == 0));
                }
            }
            tc_commit(sb + MB_EMPTY + 8 * pbuf);       // buffer free on completion
            if (kc == 1) tc_commit(sb + MB_D + 8 * (t & 1));
        }
    } else if (wid < 4) {
        // -------- consumers: LDTM + fused running argmax -----------------------
        float bv = -CUDART_INF_F;
        int bi = 0;
        int dph[2] = {0, 0};
        const uint32_t woff = ((uint32_t)(tid >> 5)) << 21;   // TMEM subpartition

        for (int t = 0; t < NT; t++) {
            mbar_wait(sb + MB_D + 8 * (t & 1), (uint32_t)dph[t & 1]);
            dph[t & 1] ^= 1;
            tc_fence_after();
            const uint32_t dt = tmem + (t & 1) * 128 + woff;
            #pragma unroll
            for (int half = 0; half < 2; half++) {
                uint32_t r0[32], r1[32];
                ldtm_x32(r0, dt + half * 64);
                ldtm_x32(r1, dt + half * 64 + 32);
                tc_wait_ld();
                const int colbase = rBase0 + t * 128 + half * 64;
                #pragma unroll
                for (int j = 0; j < 32; j++) {
                    float v = __uint_as_float(r0[j]);
                    if (v > bv) { bv = v; bi = colbase + j; }
                }
                #pragma unroll
                for (int j = 0; j < 32; j++) {
                    float v = __uint_as_float(r1[j]);
                    if (v > bv) { bv = v; bi = colbase + 32 + j; }
                }
            }
            tc_fence_before();
            if ((tid & 31) == 0) mbar_arrive(sb + MB_E + 8 * (t & 1));
        }
        atomicMax(&g_best[mBase + tid], pack_key(bv, bi));
    }

    __syncthreads();
    if (wid == 8) tc_dealloc(tmem, 256u);

#else
    // ======================= fallback (non-'a' compile pass only) ============
    // Compile-only safety net: correct but slow; the sm_103a pass is what runs.
    for (int r = 0; r < 128; r++) {
        float bv = -CUDART_INF_F;
        int bi = rBase0;
        for (int c = rBase0 + tid; c < rBase0 + NCHUNK; c += NTHREADS) {
            float dot = 0.0f;
            for (int k = 0; k < C; k++)
                dot = fmaf(A32[(size_t)k * P + mBase + r], B32[(size_t)k * P + c], dot);
            if (dot > bv) { bv = dot; bi = c; }
        }
        atomicMax(&g_best[mBase + r], pack_key(bv, bi));
    }
#endif
}

// ---------------- decode ----------------------------------------------------
__global__ void decode_kernel(float* __restrict__ out,
                              const int* __restrict__ sxp,
                              const int* __restrict__ syp,
                              int has_scale) {
    int p = blockIdx.x * blockDim.x + threadIdx.x;
    if (p >= P) return;
    int sx = has_scale ? sxp[0] : 4;
    int sy = has_scale ? syp[0] : 4;

    unsigned long long pk = g_best[p];
    int idx = 0x3FFF - (int)(pk & 0x3FFFULL);
    unsigned u = (unsigned)(pk >> 14);
    unsigned f = (u & 0x80000000u) ? (u ^ 0x80000000u) : ~u;
    float val = __uint_as_float(f);

    int h = p >> 7, w = p & 127;
    int i = idx >> 7, j = idx & 127;

    out[2 * p]     = (float)(w - j * sx);
    out[2 * p + 1] = (float)(h - i * sy);
    out[2 * P + p] = val;
}

// ---------------- launch -----------------------------------------------------
extern "C" void kernel_launch(void* const* d_in, const int* in_sizes, int n_in,
                              void* d_out, int out_size) {
    const float* A = (const float*)d_in[0];
    const float* B = (const float*)d_in[1];
    const int* sx = (n_in > 2) ? (const int*)d_in[2] : nullptr;
    const int* sy = (n_in > 3) ? (const int*)d_in[3] : nullptr;
    int has_scale = (n_in > 3) ? 1 : 0;

    cudaFuncSetAttribute(corr_kernel, cudaFuncAttributeMaxDynamicSharedMemorySize, SMEM_TOTAL);

    __nv_bfloat16* dAs;
    __nv_bfloat16* dBs;
    cudaGetSymbolAddress((void**)&dAs, g_Asp);
    cudaGetSymbolAddress((void**)&dBs, g_Bsp);

    dim3 sgrid(P / 32, C / 32), sblk(32, 8);
    split_kernel<<<sgrid, sblk>>>(A, dAs);
    split_kernel<<<sgrid, sblk>>>(B, dBs);

    init_best_kernel<<<(P + 255) / 256, 256>>>();

    dim3 grid(P / 128, NSPL);   // 96 x 3 = 288 CTAs
    corr_kernel<<<grid, NTHREADS, SMEM_TOTAL>>>(A, B);

    decode_kernel<<<(P + 255) / 256, 256>>>((float*)d_out, sx, sy, has_scale);
}